// round 7
// baseline (speedup 1.0000x reference)
#include <cuda_runtime.h>
#include <cuda_bf16.h>
#include <cuda_fp16.h>
#include <cstring>

// Problem constants
#define DIMV 128
#define NTYPES 32
#define MAXV 50048
#define MAXVP 53248
#define MAXE 650000

// Scratch
__device__ __nv_bfloat16 g_a_hi[(size_t)MAXV * DIMV];
__device__ __nv_bfloat16 g_a_lo[(size_t)MAXV * DIMV];
__device__ char  g_w_img[2 * 73728];          // smem-image of both W (hi+lo, padded)
__device__ __half g_src_h[(size_t)MAXV * DIMV];
__device__ __half g_dest_h[(size_t)MAXV * DIMV];
__device__ int   g_cnt[MAXVP];
__device__ int   g_starts[MAXVP];
__device__ int   g_cursor[MAXVP];
__device__ int2  g_srccls[MAXE];

// ---------------------------------------------------------------------------
__global__ void zero_cnt_kernel() {
    int i = blockIdx.x * blockDim.x + threadIdx.x;
    if (i < MAXVP) g_cnt[i] = 0;
}

__global__ void hist_kernel(const int* __restrict__ edst, int E) {
    int i = blockIdx.x * blockDim.x + threadIdx.x;
    if (i < E) atomicAdd(&g_cnt[edst[i]], 1);
}

// Single-block fused scan over g_cnt[MAXVP] -> g_starts, g_cursor
#define SCAN_T 1024
#define SCAN_PER 52            // 1024 * 52 = 53248
__global__ __launch_bounds__(SCAN_T) void scan_fused_kernel() {
    __shared__ int wsum[32];
    const int t = threadIdx.x, lane = t & 31, wid = t >> 5;
    const int base = t * SCAN_PER;
    int local = 0;
#pragma unroll 4
    for (int i = 0; i < SCAN_PER; i++) local += g_cnt[base + i];
    int incl = local;
#pragma unroll
    for (int o = 1; o < 32; o <<= 1) {
        int n = __shfl_up_sync(0xffffffffu, incl, o);
        if (lane >= o) incl += n;
    }
    if (lane == 31) wsum[wid] = incl;
    __syncthreads();
    if (wid == 0) {
        int ws = wsum[lane];
#pragma unroll
        for (int o = 1; o < 32; o <<= 1) {
            int n = __shfl_up_sync(0xffffffffu, ws, o);
            if (lane >= o) ws += n;
        }
        wsum[lane] = ws;
    }
    __syncthreads();
    int run = incl - local + (wid > 0 ? wsum[wid - 1] : 0);
#pragma unroll 4
    for (int i = 0; i < SCAN_PER; i++) {
        int s = g_cnt[base + i];
        g_starts[base + i] = run;
        g_cursor[base + i] = run;
        run += s;
    }
}

__global__ void build_kernel(const int* __restrict__ esrc,
                             const int* __restrict__ edst,
                             const int* __restrict__ ecls, int E) {
    int i = blockIdx.x * blockDim.x + threadIdx.x;
    if (i < E) {
        int d = edst[i];
        int pos = atomicAdd(&g_cursor[d], 1);
        g_srccls[pos] = make_int2(esrc[i], ecls[i]);
    }
}

// ---------------------------------------------------------------------------
// Split helpers
// ---------------------------------------------------------------------------
__device__ __forceinline__ void split_bf(float x, __nv_bfloat16& h, __nv_bfloat16& l) {
    h = __float2bfloat16_rn(x);
    l = __float2bfloat16_rn(x - __bfloat162float(h));
}

__device__ __forceinline__ unsigned pack_bf2(__nv_bfloat16 a, __nv_bfloat16 b) {
    __nv_bfloat162 t = __halves2bfloat162(a, b);
    unsigned u;
    memcpy(&u, &t, 4);
    return u;
}

// Preconvert node_values -> flat bf16 hi/lo  (rows >= V zero-filled)
__global__ void a_split_kernel(const float* __restrict__ nv, int V) {
    int idx = blockIdx.x * blockDim.x + threadIdx.x;   // over MAXV * 32 float4s
    if (idx >= MAXV * 32) return;
    int r = idx >> 5, q = idx & 31;
    float4 v = make_float4(0.f, 0.f, 0.f, 0.f);
    if (r < V) v = reinterpret_cast<const float4*>(nv)[(size_t)r * 32 + q];
    __nv_bfloat16 h0, h1, h2, h3, l0, l1, l2, l3;
    split_bf(v.x, h0, l0); split_bf(v.y, h1, l1);
    split_bf(v.z, h2, l2); split_bf(v.w, h3, l3);
    size_t o = (size_t)r * 128 + q * 4;
    *reinterpret_cast<uint2*>(&g_a_hi[o]) = make_uint2(pack_bf2(h0, h1), pack_bf2(h2, h3));
    *reinterpret_cast<uint2*>(&g_a_lo[o]) = make_uint2(pack_bf2(l0, l1), pack_bf2(l2, l3));
}

// Preconvert both W into the padded smem image:
// per matrix (stride 73728): hi: [nHalf][k*144 + (n&63)*2], lo at +36864
__global__ void w_split_kernel(const float* __restrict__ Wsrc,
                               const float* __restrict__ Wdst) {
    int idx = blockIdx.x * blockDim.x + threadIdx.x;   // 2 * 128 * 128
    if (idx >= 2 * 128 * 128) return;
    int m = idx >> 14;
    int e = idx & 16383;
    int k = e >> 7, n = e & 127;
    float v = (m ? Wdst : Wsrc)[e];
    __nv_bfloat16 h, l;
    split_bf(v, h, l);
    size_t base = (size_t)m * 73728 + (n >> 6) * 18432 + k * 144 + (n & 63) * 2;
    *reinterpret_cast<__nv_bfloat16*>(g_w_img + base) = h;
    *reinterpret_cast<__nv_bfloat16*>(g_w_img + base + 36864) = l;
}

// ---------------------------------------------------------------------------
// Tensor-core projection (bf16 hi/lo x3). CTA: 64 rows x 128 cols, one W
// matrix (blockIdx.y). Smem: A hi/lo 36864 + W hi/lo 73728 = 110592 ->
// 2 CTAs/SM. Prologue is pure 16B copies (all converts precomputed).
// Warp grid 2(M) x 4(N), warp tile 32x32. Epilogue stores fp16.
// ---------------------------------------------------------------------------
#define TROWS 64
#define A_HI  0
#define A_LO  18432              // A buffer: 2 halves x (64 rows x 144B) = 18432
#define W_OFF 36864
#define PROJ_SMEM 110592

#define LDSM4(r0, r1, r2, r3, addr) \
    asm volatile("ldmatrix.sync.aligned.m8n8.x4.shared.b16 {%0,%1,%2,%3}, [%4];" \
        : "=r"(r0), "=r"(r1), "=r"(r2), "=r"(r3) : "r"(addr))

#define LDSM4T(r0, r1, r2, r3, addr) \
    asm volatile("ldmatrix.sync.aligned.m8n8.x4.trans.shared.b16 {%0,%1,%2,%3}, [%4];" \
        : "=r"(r0), "=r"(r1), "=r"(r2), "=r"(r3) : "r"(addr))

#define MMA16816(d, a, b0, b1) \
    asm volatile("mma.sync.aligned.m16n8k16.row.col.f32.bf16.bf16.f32 " \
        "{%0,%1,%2,%3}, {%4,%5,%6,%7}, {%8,%9}, {%0,%1,%2,%3};" \
        : "+f"(d[0]), "+f"(d[1]), "+f"(d[2]), "+f"(d[3]) \
        : "r"(a[0]), "r"(a[1]), "r"(a[2]), "r"(a[3]), "r"(b0), "r"(b1))

__global__ __launch_bounds__(256, 2) void proj_kernel(
    int V, const float* __restrict__ bsrc, const float* __restrict__ bdst)
{
    extern __shared__ __align__(16) char smem[];
    unsigned smemu;
    asm("{ .reg .u64 t; cvta.to.shared.u64 t, %1; cvt.u32.u64 %0, t; }"
        : "=r"(smemu) : "l"(smem));

    const int tid = threadIdx.x;
    const int row0 = blockIdx.x * TROWS;
    const int wSel = blockIdx.y;

    // ---- stage A hi/lo: 64 rows x 128 bf16 = 1024 uint4 chunks per buffer.
    // chunk idx -> (r = idx>>4, c16 = idx&15); k-range of chunk = c16*8..c16*8+7
    // dest: half h = c16>>3, in-half chunk c16&7 ->
    //       byte = h*9216 + r*144 + (c16&7)*16
    {
        const uint4* ah = reinterpret_cast<const uint4*>(&g_a_hi[(size_t)row0 * 128]);
        const uint4* al = reinterpret_cast<const uint4*>(&g_a_lo[(size_t)row0 * 128]);
        for (int idx = tid; idx < 1024; idx += 256) {
            int r = idx >> 4, c16 = idx & 15;
            uint4 vh = ah[idx];
            uint4 vl = al[idx];
            size_t dst = (size_t)(c16 >> 3) * 9216 + r * 144 + (c16 & 7) * 16;
            *reinterpret_cast<uint4*>(smem + A_HI + dst) = vh;
            *reinterpret_cast<uint4*>(smem + A_LO + dst) = vl;
        }
    }
    // ---- stage W (linear copy of precomputed image) ----
    {
        const uint4* wsrc = reinterpret_cast<const uint4*>(g_w_img + wSel * 73728);
        uint4* wdst = reinterpret_cast<uint4*>(smem + W_OFF);
        for (int idx = tid; idx < 4608; idx += 256) wdst[idx] = wsrc[idx];
    }
    __syncthreads();

    const float* __restrict__ bias = wSel ? bdst : bsrc;
    __half* __restrict__ outh = wSel ? g_dest_h : g_src_h;

    const int lane = tid & 31, wid = tid >> 5;
    const int warp_m = wid >> 2;          // 0..1 : 32-row slice
    const int warp_n = wid & 3;           // 0..3 : 32-col slice
    const int sel = lane >> 3, li = lane & 7;

    const unsigned wB = smemu + W_OFF + (warp_n >> 1) * 18432;
    const int ncol0 = (warp_n & 1) * 32;

    float acc[2][4][4];
#pragma unroll
    for (int j = 0; j < 4; j++) {
        int col = warp_n * 32 + j * 8 + (lane & 3) * 2;
        float b0 = bias[col], b1 = bias[col + 1];
#pragma unroll
        for (int m = 0; m < 2; m++) {
            acc[m][j][0] = b0; acc[m][j][1] = b1;
            acc[m][j][2] = b0; acc[m][j][3] = b1;
        }
    }

#pragma unroll
    for (int h = 0; h < 2; h++) {
#pragma unroll
        for (int kf = 0; kf < 4; kf++) {
            unsigned ah[2][4], al[2][4];
            {
                int arow = warp_m * 32 + li + (sel & 1) * 8;
                int kch = kf * 16 + (sel >> 1) * 8;
                unsigned a0 = smemu + A_HI + h * 9216 + arow * 144 + kch * 2;
                LDSM4(ah[0][0], ah[0][1], ah[0][2], ah[0][3], a0);
                LDSM4(ah[1][0], ah[1][1], ah[1][2], ah[1][3], a0 + 16 * 144);
                unsigned a1 = a0 + (A_LO - A_HI);
                LDSM4(al[0][0], al[0][1], al[0][2], al[0][3], a1);
                LDSM4(al[1][0], al[1][1], al[1][2], al[1][3], a1 + 16 * 144);
            }
            const int krow = h * 64 + kf * 16 + li + (sel & 1) * 8;
#pragma unroll
            for (int jj = 0; jj < 2; jj++) {
                unsigned bh[4], bl[4];
                int nch = ncol0 + jj * 16 + (sel >> 1) * 8;
                unsigned boff = wB + krow * 144 + nch * 2;
                LDSM4T(bh[0], bh[1], bh[2], bh[3], boff);
                LDSM4T(bl[0], bl[1], bl[2], bl[3], boff + 36864);
#pragma unroll
                for (int m = 0; m < 2; m++) {
                    MMA16816(acc[m][2 * jj + 0], ah[m], bh[0], bh[1]);
                    MMA16816(acc[m][2 * jj + 1], ah[m], bh[2], bh[3]);
                    MMA16816(acc[m][2 * jj + 0], ah[m], bl[0], bl[1]);
                    MMA16816(acc[m][2 * jj + 1], ah[m], bl[2], bl[3]);
                    MMA16816(acc[m][2 * jj + 0], al[m], bh[0], bh[1]);
                    MMA16816(acc[m][2 * jj + 1], al[m], bh[2], bh[3]);
                }
            }
        }
    }

    // epilogue: fp16 stores (outh rows up to MAXV, tile rows always in-bounds)
#pragma unroll
    for (int m = 0; m < 2; m++) {
        int rlo = row0 + warp_m * 32 + m * 16 + (lane >> 2);
#pragma unroll
        for (int j = 0; j < 4; j++) {
            int col = warp_n * 32 + j * 8 + (lane & 3) * 2;
            *reinterpret_cast<__half2*>(&outh[(size_t)rlo * 128 + col]) =
                __floats2half2_rn(acc[m][j][0], acc[m][j][1]);
            *reinterpret_cast<__half2*>(&outh[(size_t)(rlo + 8) * 128 + col]) =
                __floats2half2_rn(acc[m][j][2], acc[m][j][3]);
        }
    }
}

// ---------------------------------------------------------------------------
// Segment-accumulate: one warp per dest node; fp16 gathers (8B/lane),
// fp32 accumulation, single non-atomic fp32 store.
// ---------------------------------------------------------------------------
__device__ __forceinline__ float4 h4_to_f4(uint2 u) {
    __half2 h0, h1;
    memcpy(&h0, &u.x, 4);
    memcpy(&h1, &u.y, 4);
    float2 f0 = __half22float2(h0);
    float2 f1 = __half22float2(h1);
    return make_float4(f0.x, f0.y, f1.x, f1.y);
}

__global__ __launch_bounds__(256) void accum_kernel(
    const float* __restrict__ emb, float* __restrict__ out, int V)
{
    __shared__ float4 emb_sm[NTYPES * 32];
    const int tid = threadIdx.x;
    for (int i = tid; i < NTYPES * 32; i += 256)
        emb_sm[i] = reinterpret_cast<const float4*>(emb)[i];
    __syncthreads();

    const int lane = tid & 31;
    const int d = (blockIdx.x * 256 + tid) >> 5;
    if (d >= V) return;

    const int base = g_starts[d];
    const int n    = g_starts[d + 1] - base;   // counts beyond V are 0

    const uint2* __restrict__ sph = reinterpret_cast<const uint2*>(g_src_h);
    const uint2* __restrict__ dph = reinterpret_cast<const uint2*>(g_dest_h);

    const float4 dv = h4_to_f4(dph[(size_t)d * 32 + lane]);
    float4 acc = make_float4(0.f, 0.f, 0.f, 0.f);

    for (int j0 = 0; j0 < n; j0 += 32) {
        const int m = min(32, n - j0);
        int2 sc = make_int2(0, 0);
        if (lane < m) sc = g_srccls[base + j0 + lane];

        int s0 = __shfl_sync(0xffffffffu, sc.x, 0);
        uint2 a = sph[(size_t)s0 * 32 + lane];

        for (int j = 0; j < m; j++) {
            uint2 an = a;
            if (j + 1 < m) {
                int sn = __shfl_sync(0xffffffffu, sc.x, j + 1);
                an = sph[(size_t)sn * 32 + lane];
            }
            const int c = __shfl_sync(0xffffffffu, sc.y, j);
            const float4 e = emb_sm[c * 32 + lane];
            const float4 af = h4_to_f4(a);
            acc.x += fmaxf(af.x + dv.x + e.x, 0.f);
            acc.y += fmaxf(af.y + dv.y + e.y, 0.f);
            acc.z += fmaxf(af.z + dv.z + e.z, 0.f);
            acc.w += fmaxf(af.w + dv.w + e.w, 0.f);
            a = an;
        }
    }

    reinterpret_cast<float4*>(out)[(size_t)d * 32 + lane] = acc;
}

// ---------------------------------------------------------------------------
// Launch. proj at index 3 (ncu profiles launch #3).
// ---------------------------------------------------------------------------
extern "C" void kernel_launch(void* const* d_in, const int* in_sizes, int n_in,
                              void* d_out, int out_size) {
    const float* nv   = (const float*)d_in[0];
    const int*   esrc = (const int*)  d_in[1];
    const int*   edst = (const int*)  d_in[2];
    const int*   ecls = (const int*)  d_in[3];
    const float* Wsrc = (const float*)d_in[4];
    const float* bsrc = (const float*)d_in[5];
    const float* Wdst = (const float*)d_in[6];
    const float* bdst = (const float*)d_in[7];
    const float* emb  = (const float*)d_in[8];
    float* out = (float*)d_out;

    const int V = in_sizes[0] / DIMV;
    const int E = in_sizes[1];

    cudaFuncSetAttribute(proj_kernel, cudaFuncAttributeMaxDynamicSharedMemorySize,
                         PROJ_SMEM);

    zero_cnt_kernel<<<(MAXVP + 255) / 256, 256>>>();                    // 0
    w_split_kernel<<<(2 * 128 * 128 + 255) / 256, 256>>>(Wsrc, Wdst);   // 1
    a_split_kernel<<<(MAXV * 32 + 255) / 256, 256>>>(nv, V);            // 2
    {
        dim3 grid((V + TROWS - 1) / TROWS, 2);
        proj_kernel<<<grid, 256, PROJ_SMEM>>>(V, bsrc, bdst);           // 3
    }
    hist_kernel<<<(E + 255) / 256, 256>>>(edst, E);                     // 4
    scan_fused_kernel<<<1, SCAN_T>>>();                                 // 5
    build_kernel<<<(E + 255) / 256, 256>>>(esrc, edst, ecls, E);        // 6
    accum_kernel<<<(V * 32 + 255) / 256, 256>>>(emb, out, V);           // 7
}

// round 8
// speedup vs baseline: 1.3079x; 1.3079x over previous
#include <cuda_runtime.h>
#include <cuda_bf16.h>
#include <cuda_fp16.h>
#include <cstring>

// Problem constants
#define DIMV 128
#define NTYPES 32
#define MAXV 50048
#define MAXVP 53248          // 52 * 1024
#define MAXE 650000

// Scratch
__device__ __nv_bfloat16 g_a_hi[(size_t)MAXV * DIMV];
__device__ __nv_bfloat16 g_a_lo[(size_t)MAXV * DIMV];
__device__ char  g_w_img[2 * 73728];
__device__ __half g_src_h[(size_t)MAXV * DIMV];
__device__ __half g_dest_h[(size_t)MAXV * DIMV];
__device__ int   g_cnt[MAXVP];
__device__ int   g_starts[MAXVP];
__device__ int   g_cursor[MAXVP];
__device__ int2  g_srccls[MAXE];

// ---------------------------------------------------------------------------
// Split helpers
// ---------------------------------------------------------------------------
__device__ __forceinline__ void split_bf(float x, __nv_bfloat16& h, __nv_bfloat16& l) {
    h = __float2bfloat16_rn(x);
    l = __float2bfloat16_rn(x - __bfloat162float(h));
}

__device__ __forceinline__ unsigned pack_bf2(__nv_bfloat16 a, __nv_bfloat16 b) {
    __nv_bfloat162 t = __halves2bfloat162(a, b);
    unsigned u;
    memcpy(&u, &t, 4);
    return u;
}

// ---------------------------------------------------------------------------
// Fused pre-pass: zero hist counters + split W into padded smem image +
// split node_values into bf16 hi/lo. Disjoint tasks by global index.
// ---------------------------------------------------------------------------
__global__ void pre_kernel(const float* __restrict__ nv, int V,
                           const float* __restrict__ Wsrc,
                           const float* __restrict__ Wdst) {
    int idx = blockIdx.x * blockDim.x + threadIdx.x;

    if (idx < MAXVP) g_cnt[idx] = 0;

    if (idx < 2 * 128 * 128) {
        int m = idx >> 14;
        int e = idx & 16383;
        int k = e >> 7, n = e & 127;
        float v = (m ? Wdst : Wsrc)[e];
        __nv_bfloat16 h, l;
        split_bf(v, h, l);
        size_t base = (size_t)m * 73728 + (n >> 6) * 18432 + k * 144 + (n & 63) * 2;
        *reinterpret_cast<__nv_bfloat16*>(g_w_img + base) = h;
        *reinterpret_cast<__nv_bfloat16*>(g_w_img + base + 36864) = l;
    }

    if (idx < MAXV * 32) {
        int r = idx >> 5, q = idx & 31;
        float4 v = make_float4(0.f, 0.f, 0.f, 0.f);
        if (r < V) v = reinterpret_cast<const float4*>(nv)[(size_t)r * 32 + q];
        __nv_bfloat16 h0, h1, h2, h3, l0, l1, l2, l3;
        split_bf(v.x, h0, l0); split_bf(v.y, h1, l1);
        split_bf(v.z, h2, l2); split_bf(v.w, h3, l3);
        size_t o = (size_t)r * 128 + q * 4;
        *reinterpret_cast<uint2*>(&g_a_hi[o]) =
            make_uint2(pack_bf2(h0, h1), pack_bf2(h2, h3));
        *reinterpret_cast<uint2*>(&g_a_lo[o]) =
            make_uint2(pack_bf2(l0, l1), pack_bf2(l2, l3));
    }
}

// ---------------------------------------------------------------------------
__global__ void hist_kernel(const int* __restrict__ edst, int E) {
    int i = blockIdx.x * blockDim.x + threadIdx.x;
    if (i < E) atomicAdd(&g_cnt[edst[i]], 1);
}

// ---------------------------------------------------------------------------
// Single-block tiled scan: 52 tiles x 1024 COALESCED elements.
// Parity-buffered warp sums; register carry.
// ---------------------------------------------------------------------------
__global__ __launch_bounds__(1024) void scan_kernel() {
    __shared__ int wsums[2][32];
    const int t = threadIdx.x, lane = t & 31, wid = t >> 5;
    int carry = 0;
    int p = 0;
    for (int tile = 0; tile < MAXVP; tile += 1024, p ^= 1) {
        int idx = tile + t;
        int v = g_cnt[idx];
        int incl = v;
#pragma unroll
        for (int o = 1; o < 32; o <<= 1) {
            int n = __shfl_up_sync(0xffffffffu, incl, o);
            if (lane >= o) incl += n;
        }
        if (lane == 31) wsums[p][wid] = incl;
        __syncthreads();
        if (wid == 0) {
            int ws = wsums[p][lane];
#pragma unroll
            for (int o = 1; o < 32; o <<= 1) {
                int n = __shfl_up_sync(0xffffffffu, ws, o);
                if (lane >= o) ws += n;
            }
            wsums[p][lane] = ws;
        }
        __syncthreads();
        int excl = incl - v + (wid ? wsums[p][wid - 1] : 0) + carry;
        g_starts[idx] = excl;
        g_cursor[idx] = excl;
        carry += wsums[p][31];
    }
}

// ---------------------------------------------------------------------------
__global__ void build_kernel(const int* __restrict__ esrc,
                             const int* __restrict__ edst,
                             const int* __restrict__ ecls, int E) {
    int i = blockIdx.x * blockDim.x + threadIdx.x;
    if (i < E) {
        int d = edst[i];
        int pos = atomicAdd(&g_cursor[d], 1);
        g_srccls[pos] = make_int2(esrc[i], ecls[i]);
    }
}

// ---------------------------------------------------------------------------
// Tensor-core projection (bf16 hi/lo x3), unchanged from round 7 (passing).
// ---------------------------------------------------------------------------
#define TROWS 64
#define A_HI  0
#define A_LO  18432
#define W_OFF 36864
#define PROJ_SMEM 110592

#define LDSM4(r0, r1, r2, r3, addr) \
    asm volatile("ldmatrix.sync.aligned.m8n8.x4.shared.b16 {%0,%1,%2,%3}, [%4];" \
        : "=r"(r0), "=r"(r1), "=r"(r2), "=r"(r3) : "r"(addr))

#define LDSM4T(r0, r1, r2, r3, addr) \
    asm volatile("ldmatrix.sync.aligned.m8n8.x4.trans.shared.b16 {%0,%1,%2,%3}, [%4];" \
        : "=r"(r0), "=r"(r1), "=r"(r2), "=r"(r3) : "r"(addr))

#define MMA16816(d, a, b0, b1) \
    asm volatile("mma.sync.aligned.m16n8k16.row.col.f32.bf16.bf16.f32 " \
        "{%0,%1,%2,%3}, {%4,%5,%6,%7}, {%8,%9}, {%0,%1,%2,%3};" \
        : "+f"(d[0]), "+f"(d[1]), "+f"(d[2]), "+f"(d[3]) \
        : "r"(a[0]), "r"(a[1]), "r"(a[2]), "r"(a[3]), "r"(b0), "r"(b1))

__global__ __launch_bounds__(256, 2) void proj_kernel(
    int V, const float* __restrict__ bsrc, const float* __restrict__ bdst)
{
    extern __shared__ __align__(16) char smem[];
    unsigned smemu;
    asm("{ .reg .u64 t; cvta.to.shared.u64 t, %1; cvt.u32.u64 %0, t; }"
        : "=r"(smemu) : "l"(smem));

    const int tid = threadIdx.x;
    const int row0 = blockIdx.x * TROWS;
    const int wSel = blockIdx.y;

    // stage A hi/lo: 1024 uint4 chunks per buffer
    {
        const uint4* ah = reinterpret_cast<const uint4*>(&g_a_hi[(size_t)row0 * 128]);
        const uint4* al = reinterpret_cast<const uint4*>(&g_a_lo[(size_t)row0 * 128]);
        for (int idx = tid; idx < 1024; idx += 256) {
            int r = idx >> 4, c16 = idx & 15;
            uint4 vh = ah[idx];
            uint4 vl = al[idx];
            size_t dst = (size_t)(c16 >> 3) * 9216 + r * 144 + (c16 & 7) * 16;
            *reinterpret_cast<uint4*>(smem + A_HI + dst) = vh;
            *reinterpret_cast<uint4*>(smem + A_LO + dst) = vl;
        }
    }
    // stage W (linear copy of precomputed image)
    {
        const uint4* wsrc = reinterpret_cast<const uint4*>(g_w_img + wSel * 73728);
        uint4* wdst = reinterpret_cast<uint4*>(smem + W_OFF);
        for (int idx = tid; idx < 4608; idx += 256) wdst[idx] = wsrc[idx];
    }
    __syncthreads();

    const float* __restrict__ bias = wSel ? bdst : bsrc;
    __half* __restrict__ outh = wSel ? g_dest_h : g_src_h;

    const int lane = tid & 31, wid = tid >> 5;
    const int warp_m = wid >> 2;
    const int warp_n = wid & 3;
    const int sel = lane >> 3, li = lane & 7;

    const unsigned wB = smemu + W_OFF + (warp_n >> 1) * 18432;
    const int ncol0 = (warp_n & 1) * 32;

    float acc[2][4][4];
#pragma unroll
    for (int j = 0; j < 4; j++) {
        int col = warp_n * 32 + j * 8 + (lane & 3) * 2;
        float b0 = bias[col], b1 = bias[col + 1];
#pragma unroll
        for (int m = 0; m < 2; m++) {
            acc[m][j][0] = b0; acc[m][j][1] = b1;
            acc[m][j][2] = b0; acc[m][j][3] = b1;
        }
    }

#pragma unroll
    for (int h = 0; h < 2; h++) {
#pragma unroll
        for (int kf = 0; kf < 4; kf++) {
            unsigned ah[2][4], al[2][4];
            {
                int arow = warp_m * 32 + li + (sel & 1) * 8;
                int kch = kf * 16 + (sel >> 1) * 8;
                unsigned a0 = smemu + A_HI + h * 9216 + arow * 144 + kch * 2;
                LDSM4(ah[0][0], ah[0][1], ah[0][2], ah[0][3], a0);
                LDSM4(ah[1][0], ah[1][1], ah[1][2], ah[1][3], a0 + 16 * 144);
                unsigned a1 = a0 + (A_LO - A_HI);
                LDSM4(al[0][0], al[0][1], al[0][2], al[0][3], a1);
                LDSM4(al[1][0], al[1][1], al[1][2], al[1][3], a1 + 16 * 144);
            }
            const int krow = h * 64 + kf * 16 + li + (sel & 1) * 8;
#pragma unroll
            for (int jj = 0; jj < 2; jj++) {
                unsigned bh[4], bl[4];
                int nch = ncol0 + jj * 16 + (sel >> 1) * 8;
                unsigned boff = wB + krow * 144 + nch * 2;
                LDSM4T(bh[0], bh[1], bh[2], bh[3], boff);
                LDSM4T(bl[0], bl[1], bl[2], bl[3], boff + 36864);
#pragma unroll
                for (int m = 0; m < 2; m++) {
                    MMA16816(acc[m][2 * jj + 0], ah[m], bh[0], bh[1]);
                    MMA16816(acc[m][2 * jj + 1], ah[m], bh[2], bh[3]);
                    MMA16816(acc[m][2 * jj + 0], ah[m], bl[0], bl[1]);
                    MMA16816(acc[m][2 * jj + 1], ah[m], bl[2], bl[3]);
                    MMA16816(acc[m][2 * jj + 0], al[m], bh[0], bh[1]);
                    MMA16816(acc[m][2 * jj + 1], al[m], bh[2], bh[3]);
                }
            }
        }
    }

#pragma unroll
    for (int m = 0; m < 2; m++) {
        int rlo = row0 + warp_m * 32 + m * 16 + (lane >> 2);
#pragma unroll
        for (int j = 0; j < 4; j++) {
            int col = warp_n * 32 + j * 8 + (lane & 3) * 2;
            *reinterpret_cast<__half2*>(&outh[(size_t)rlo * 128 + col]) =
                __floats2half2_rn(acc[m][j][0], acc[m][j][1]);
            *reinterpret_cast<__half2*>(&outh[(size_t)(rlo + 8) * 128 + col]) =
                __floats2half2_rn(acc[m][j][2], acc[m][j][3]);
        }
    }
}

// ---------------------------------------------------------------------------
// Segment-accumulate: warp per dest node, fp16 gathers, depth-3 pipeline
// (two gathers in flight), fp32 accumulation, non-atomic store.
// ---------------------------------------------------------------------------
__device__ __forceinline__ float4 h4_to_f4(uint2 u) {
    __half2 h0, h1;
    memcpy(&h0, &u.x, 4);
    memcpy(&h1, &u.y, 4);
    float2 f0 = __half22float2(h0);
    float2 f1 = __half22float2(h1);
    return make_float4(f0.x, f0.y, f1.x, f1.y);
}

__global__ __launch_bounds__(256) void accum_kernel(
    const float* __restrict__ emb, float* __restrict__ out, int V)
{
    __shared__ float4 emb_sm[NTYPES * 32];
    const int tid = threadIdx.x;
    for (int i = tid; i < NTYPES * 32; i += 256)
        emb_sm[i] = reinterpret_cast<const float4*>(emb)[i];
    __syncthreads();

    const int lane = tid & 31;
    const int d = (blockIdx.x * 256 + tid) >> 5;
    if (d >= V) return;

    const int base = g_starts[d];
    const int n    = g_starts[d + 1] - base;

    const uint2* __restrict__ sph = reinterpret_cast<const uint2*>(g_src_h);
    const uint2* __restrict__ dph = reinterpret_cast<const uint2*>(g_dest_h);

    const float4 dv = h4_to_f4(dph[(size_t)d * 32 + lane]);
    float4 acc = make_float4(0.f, 0.f, 0.f, 0.f);

    for (int j0 = 0; j0 < n; j0 += 32) {
        const int m = min(32, n - j0);
        int2 sc = make_int2(0, 0);
        if (lane < m) sc = g_srccls[base + j0 + lane];

        uint2 a0, a1;
        {
            int s = __shfl_sync(0xffffffffu, sc.x, 0);
            a0 = sph[(size_t)s * 32 + lane];
        }
        a1 = a0;
        if (m > 1) {
            int s = __shfl_sync(0xffffffffu, sc.x, 1);
            a1 = sph[(size_t)s * 32 + lane];
        }

        for (int j = 0; j < m; j++) {
            uint2 an = a1;
            if (j + 2 < m) {
                int s = __shfl_sync(0xffffffffu, sc.x, j + 2);
                an = sph[(size_t)s * 32 + lane];
            }
            const int c = __shfl_sync(0xffffffffu, sc.y, j);
            const float4 e = emb_sm[c * 32 + lane];
            const float4 af = h4_to_f4(a0);
            acc.x += fmaxf(af.x + dv.x + e.x, 0.f);
            acc.y += fmaxf(af.y + dv.y + e.y, 0.f);
            acc.z += fmaxf(af.z + dv.z + e.z, 0.f);
            acc.w += fmaxf(af.w + dv.w + e.w, 0.f);
            a0 = a1;
            a1 = an;
        }
    }

    reinterpret_cast<float4*>(out)[(size_t)d * 32 + lane] = acc;
}

// ---------------------------------------------------------------------------
// Launch: pre(0), hist(1), proj(2), scan(3), build(4), accum(5).
// scan lands at ncu capture index 3 (verify the fix: predict ~8us).
// ---------------------------------------------------------------------------
extern "C" void kernel_launch(void* const* d_in, const int* in_sizes, int n_in,
                              void* d_out, int out_size) {
    const float* nv   = (const float*)d_in[0];
    const int*   esrc = (const int*)  d_in[1];
    const int*   edst = (const int*)  d_in[2];
    const int*   ecls = (const int*)  d_in[3];
    const float* Wsrc = (const float*)d_in[4];
    const float* bsrc = (const float*)d_in[5];
    const float* Wdst = (const float*)d_in[6];
    const float* bdst = (const float*)d_in[7];
    const float* emb  = (const float*)d_in[8];
    float* out = (float*)d_out;

    const int V = in_sizes[0] / DIMV;
    const int E = in_sizes[1];

    cudaFuncSetAttribute(proj_kernel, cudaFuncAttributeMaxDynamicSharedMemorySize,
                         PROJ_SMEM);

    pre_kernel<<<(MAXV * 32 + 255) / 256, 256>>>(nv, V, Wsrc, Wdst);    // 0
    hist_kernel<<<(E + 255) / 256, 256>>>(edst, E);                     // 1
    {
        dim3 grid((V + TROWS - 1) / TROWS, 2);
        proj_kernel<<<grid, 256, PROJ_SMEM>>>(V, bsrc, bdst);           // 2
    }
    scan_kernel<<<1, 1024>>>();                                         // 3
    build_kernel<<<(E + 255) / 256, 256>>>(esrc, edst, ecls, E);        // 4
    accum_kernel<<<(V * 32 + 255) / 256, 256>>>(emb, out, V);           // 5
}

// round 10
// speedup vs baseline: 1.7838x; 1.3639x over previous
#include <cuda_runtime.h>
#include <cuda_bf16.h>
#include <cuda_fp16.h>
#include <cstring>

// Problem constants
#define DIMV 128
#define NTYPES 32
#define MAXV 50048
#define MAXVP 53248          // 52 * 1024
#define MAXE 650000
#define SCAN_NB 52

// Scratch
__device__ __nv_bfloat16 g_a_hi[(size_t)MAXV * DIMV];
__device__ __nv_bfloat16 g_a_lo[(size_t)MAXV * DIMV];
__device__ char  g_w_img[2 * 73728];
__device__ __half g_src_h[(size_t)MAXV * DIMV];
__device__ __half g_dest_h[(size_t)MAXV * DIMV];
__device__ int   g_cnt[MAXVP];
__device__ int   g_starts[MAXVP];
__device__ int   g_cursor[MAXVP];
__device__ int   g_bsum[64];
__device__ int2  g_srccls[MAXE];

// ---------------------------------------------------------------------------
// Split helpers
// ---------------------------------------------------------------------------
__device__ __forceinline__ void split_bf(float x, __nv_bfloat16& h, __nv_bfloat16& l) {
    h = __float2bfloat16_rn(x);
    l = __float2bfloat16_rn(x - __bfloat162float(h));
}

__device__ __forceinline__ unsigned pack_bf2(__nv_bfloat16 a, __nv_bfloat16 b) {
    __nv_bfloat162 t = __halves2bfloat162(a, b);
    unsigned u;
    memcpy(&u, &t, 4);
    return u;
}

// ---------------------------------------------------------------------------
// Fused pre-pass: zero hist counters + split W + split node_values.
// ---------------------------------------------------------------------------
__global__ void pre_kernel(const float* __restrict__ nv, int V,
                           const float* __restrict__ Wsrc,
                           const float* __restrict__ Wdst) {
    int idx = blockIdx.x * blockDim.x + threadIdx.x;

    if (idx < MAXVP) g_cnt[idx] = 0;

    if (idx < 2 * 128 * 128) {
        int m = idx >> 14;
        int e = idx & 16383;
        int k = e >> 7, n = e & 127;
        float v = (m ? Wdst : Wsrc)[e];
        __nv_bfloat16 h, l;
        split_bf(v, h, l);
        size_t base = (size_t)m * 73728 + (n >> 6) * 18432 + k * 144 + (n & 63) * 2;
        *reinterpret_cast<__nv_bfloat16*>(g_w_img + base) = h;
        *reinterpret_cast<__nv_bfloat16*>(g_w_img + base + 36864) = l;
    }

    if (idx < MAXV * 32) {
        int r = idx >> 5, q = idx & 31;
        float4 v = make_float4(0.f, 0.f, 0.f, 0.f);
        if (r < V) v = reinterpret_cast<const float4*>(nv)[(size_t)r * 32 + q];
        __nv_bfloat16 h0, h1, h2, h3, l0, l1, l2, l3;
        split_bf(v.x, h0, l0); split_bf(v.y, h1, l1);
        split_bf(v.z, h2, l2); split_bf(v.w, h3, l3);
        size_t o = (size_t)r * 128 + q * 4;
        *reinterpret_cast<uint2*>(&g_a_hi[o]) =
            make_uint2(pack_bf2(h0, h1), pack_bf2(h2, h3));
        *reinterpret_cast<uint2*>(&g_a_lo[o]) =
            make_uint2(pack_bf2(l0, l1), pack_bf2(l2, l3));
    }
}

// ---------------------------------------------------------------------------
__global__ void hist_kernel(const int* __restrict__ edst, int E) {
    int i = blockIdx.x * blockDim.x + threadIdx.x;
    if (i < E) atomicAdd(&g_cnt[edst[i]], 1);
}

// ---------------------------------------------------------------------------
// Scan phase A: 52 blocks x 1024 threads; block-local exclusive scan of
// g_cnt, block total -> g_bsum[b].
// ---------------------------------------------------------------------------
__global__ __launch_bounds__(1024) void scan_a_kernel() {
    __shared__ int wsum[32];
    const int t = threadIdx.x, lane = t & 31, wid = t >> 5;
    const int idx = blockIdx.x * 1024 + t;
    int v = g_cnt[idx];
    int incl = v;
#pragma unroll
    for (int o = 1; o < 32; o <<= 1) {
        int n = __shfl_up_sync(0xffffffffu, incl, o);
        if (lane >= o) incl += n;
    }
    if (lane == 31) wsum[wid] = incl;
    __syncthreads();
    if (wid == 0) {
        int ws = wsum[lane];
#pragma unroll
        for (int o = 1; o < 32; o <<= 1) {
            int n = __shfl_up_sync(0xffffffffu, ws, o);
            if (lane >= o) ws += n;
        }
        wsum[lane] = ws;
    }
    __syncthreads();
    int excl = incl - v + (wid ? wsum[wid - 1] : 0);
    g_starts[idx] = excl;
    if (t == 1023) g_bsum[blockIdx.x] = excl + v;
}

// ---------------------------------------------------------------------------
// Scan phase B: 52 blocks; warp 0 scans the 52 block totals to get this
// block's offset, then all threads add it.
// ---------------------------------------------------------------------------
__global__ __launch_bounds__(1024) void scan_b_kernel() {
    __shared__ int excl[64];
    const int t = threadIdx.x, lane = t & 31;
    if (t < 32) {
        int v0 = g_bsum[lane];                               // lanes 0..31
        int v1 = (32 + lane < SCAN_NB) ? g_bsum[32 + lane] : 0;
        int i0 = v0;
#pragma unroll
        for (int o = 1; o < 32; o <<= 1) {
            int n = __shfl_up_sync(0xffffffffu, i0, o);
            if (lane >= o) i0 += n;
        }
        int tot0 = __shfl_sync(0xffffffffu, i0, 31);
        int i1 = v1;
#pragma unroll
        for (int o = 1; o < 32; o <<= 1) {
            int n = __shfl_up_sync(0xffffffffu, i1, o);
            if (lane >= o) i1 += n;
        }
        excl[lane] = i0 - v0;
        excl[32 + lane] = tot0 + i1 - v1;
    }
    __syncthreads();
    const int off = excl[blockIdx.x];
    const int idx = blockIdx.x * 1024 + t;
    int s = g_starts[idx] + off;
    g_starts[idx] = s;
    g_cursor[idx] = s;
}

// ---------------------------------------------------------------------------
__global__ void build_kernel(const int* __restrict__ esrc,
                             const int* __restrict__ edst,
                             const int* __restrict__ ecls, int E) {
    int i = blockIdx.x * blockDim.x + threadIdx.x;
    if (i < E) {
        int d = edst[i];
        int pos = atomicAdd(&g_cursor[d], 1);
        g_srccls[pos] = make_int2(esrc[i], ecls[i]);
    }
}

// ---------------------------------------------------------------------------
// Persistent tensor-core projection (bf16 hi/lo x3).
// Grid = 296 CTAs (2/SM). CTA: wSel = bid & 1; stages its W image ONCE,
// then loops over row tiles (64 rows each) stride 148.
// Smem: A hi/lo 36864 + W hi/lo 73728 = 110592 -> 2 CTAs/SM.
// ---------------------------------------------------------------------------
#define TROWS 64
#define A_HI  0
#define A_LO  18432
#define W_OFF 36864
#define PROJ_SMEM 110592
#define PROJ_GRID 296

#define LDSM4(r0, r1, r2, r3, addr) \
    asm volatile("ldmatrix.sync.aligned.m8n8.x4.shared.b16 {%0,%1,%2,%3}, [%4];" \
        : "=r"(r0), "=r"(r1), "=r"(r2), "=r"(r3) : "r"(addr))

#define LDSM4T(r0, r1, r2, r3, addr) \
    asm volatile("ldmatrix.sync.aligned.m8n8.x4.trans.shared.b16 {%0,%1,%2,%3}, [%4];" \
        : "=r"(r0), "=r"(r1), "=r"(r2), "=r"(r3) : "r"(addr))

#define MMA16816(d, a, b0, b1) \
    asm volatile("mma.sync.aligned.m16n8k16.row.col.f32.bf16.bf16.f32 " \
        "{%0,%1,%2,%3}, {%4,%5,%6,%7}, {%8,%9}, {%0,%1,%2,%3};" \
        : "+f"(d[0]), "+f"(d[1]), "+f"(d[2]), "+f"(d[3]) \
        : "r"(a[0]), "r"(a[1]), "r"(a[2]), "r"(a[3]), "r"(b0), "r"(b1))

__global__ __launch_bounds__(256, 2) void proj_kernel(
    int V, const float* __restrict__ bsrc, const float* __restrict__ bdst)
{
    extern __shared__ __align__(16) char smem[];
    unsigned smemu;
    asm("{ .reg .u64 t; cvta.to.shared.u64 t, %1; cvt.u32.u64 %0, t; }"
        : "=r"(smemu) : "l"(smem));

    const int tid = threadIdx.x;
    const int wSel = blockIdx.x & 1;
    const int tile0 = blockIdx.x >> 1;       // 0..147
    const int nTiles = (V + TROWS - 1) / TROWS;

    // ---- stage W ONCE (linear copy of precomputed image) ----
    {
        const uint4* wsrc = reinterpret_cast<const uint4*>(g_w_img + wSel * 73728);
        uint4* wdst = reinterpret_cast<uint4*>(smem + W_OFF);
        for (int idx = tid; idx < 4608; idx += 256) wdst[idx] = wsrc[idx];
    }

    const float* __restrict__ bias = wSel ? bdst : bsrc;
    __half* __restrict__ outh = wSel ? g_dest_h : g_src_h;

    const int lane = tid & 31, wid = tid >> 5;
    const int warp_m = wid >> 2;
    const int warp_n = wid & 3;
    const int sel = lane >> 3, li = lane & 7;

    const unsigned wB = smemu + W_OFF + (warp_n >> 1) * 18432;
    const int ncol0 = (warp_n & 1) * 32;

    // bias values hoisted (same every tile)
    float bv[4][2];
#pragma unroll
    for (int j = 0; j < 4; j++) {
        int col = warp_n * 32 + j * 8 + (lane & 3) * 2;
        bv[j][0] = bias[col];
        bv[j][1] = bias[col + 1];
    }

    for (int tile = tile0; tile < nTiles; tile += 148) {
        const int row0 = tile * TROWS;

        __syncthreads();   // previous iteration's ldmatrix reads done (also covers W on iter 0)

        // ---- stage A hi/lo: 1024 uint4 chunks per buffer ----
        {
            const uint4* ah = reinterpret_cast<const uint4*>(&g_a_hi[(size_t)row0 * 128]);
            const uint4* al = reinterpret_cast<const uint4*>(&g_a_lo[(size_t)row0 * 128]);
            for (int idx = tid; idx < 1024; idx += 256) {
                int r = idx >> 4, c16 = idx & 15;
                uint4 vh = ah[idx];
                uint4 vl = al[idx];
                size_t dst = (size_t)(c16 >> 3) * 9216 + r * 144 + (c16 & 7) * 16;
                *reinterpret_cast<uint4*>(smem + A_HI + dst) = vh;
                *reinterpret_cast<uint4*>(smem + A_LO + dst) = vl;
            }
        }
        __syncthreads();

        float acc[2][4][4];
#pragma unroll
        for (int j = 0; j < 4; j++)
#pragma unroll
            for (int m = 0; m < 2; m++) {
                acc[m][j][0] = bv[j][0]; acc[m][j][1] = bv[j][1];
                acc[m][j][2] = bv[j][0]; acc[m][j][3] = bv[j][1];
            }

#pragma unroll
        for (int h = 0; h < 2; h++) {
#pragma unroll
            for (int kf = 0; kf < 4; kf++) {
                unsigned ah[2][4], al[2][4];
                {
                    int arow = warp_m * 32 + li + (sel & 1) * 8;
                    int kch = kf * 16 + (sel >> 1) * 8;
                    unsigned a0 = smemu + A_HI + h * 9216 + arow * 144 + kch * 2;
                    LDSM4(ah[0][0], ah[0][1], ah[0][2], ah[0][3], a0);
                    LDSM4(ah[1][0], ah[1][1], ah[1][2], ah[1][3], a0 + 16 * 144);
                    unsigned a1 = a0 + (A_LO - A_HI);
                    LDSM4(al[0][0], al[0][1], al[0][2], al[0][3], a1);
                    LDSM4(al[1][0], al[1][1], al[1][2], al[1][3], a1 + 16 * 144);
                }
                const int krow = h * 64 + kf * 16 + li + (sel & 1) * 8;
#pragma unroll
                for (int jj = 0; jj < 2; jj++) {
                    unsigned bh[4], bl[4];
                    int nch = ncol0 + jj * 16 + (sel >> 1) * 8;
                    unsigned boff = wB + krow * 144 + nch * 2;
                    LDSM4T(bh[0], bh[1], bh[2], bh[3], boff);
                    LDSM4T(bl[0], bl[1], bl[2], bl[3], boff + 36864);
#pragma unroll
                    for (int m = 0; m < 2; m++) {
                        MMA16816(acc[m][2 * jj + 0], ah[m], bh[0], bh[1]);
                        MMA16816(acc[m][2 * jj + 1], ah[m], bh[2], bh[3]);
                        MMA16816(acc[m][2 * jj + 0], ah[m], bl[0], bl[1]);
                        MMA16816(acc[m][2 * jj + 1], ah[m], bl[2], bl[3]);
                        MMA16816(acc[m][2 * jj + 0], al[m], bh[0], bh[1]);
                        MMA16816(acc[m][2 * jj + 1], al[m], bh[2], bh[3]);
                    }
                }
            }
        }

        // epilogue: fp16 stores
#pragma unroll
        for (int m = 0; m < 2; m++) {
            int rlo = row0 + warp_m * 32 + m * 16 + (lane >> 2);
#pragma unroll
            for (int j = 0; j < 4; j++) {
                int col = warp_n * 32 + j * 8 + (lane & 3) * 2;
                *reinterpret_cast<__half2*>(&outh[(size_t)rlo * 128 + col]) =
                    __floats2half2_rn(acc[m][j][0], acc[m][j][1]);
                *reinterpret_cast<__half2*>(&outh[(size_t)(rlo + 8) * 128 + col]) =
                    __floats2half2_rn(acc[m][j][2], acc[m][j][3]);
            }
        }
    }
}

// ---------------------------------------------------------------------------
// Segment-accumulate: warp per dest node, fp16 gathers, depth-3 pipeline.
// ---------------------------------------------------------------------------
__device__ __forceinline__ float4 h4_to_f4(uint2 u) {
    __half2 h0, h1;
    memcpy(&h0, &u.x, 4);
    memcpy(&h1, &u.y, 4);
    float2 f0 = __half22float2(h0);
    float2 f1 = __half22float2(h1);
    return make_float4(f0.x, f0.y, f1.x, f1.y);
}

__global__ __launch_bounds__(256) void accum_kernel(
    const float* __restrict__ emb, float* __restrict__ out, int V)
{
    __shared__ float4 emb_sm[NTYPES * 32];
    const int tid = threadIdx.x;
    for (int i = tid; i < NTYPES * 32; i += 256)
        emb_sm[i] = reinterpret_cast<const float4*>(emb)[i];
    __syncthreads();

    const int lane = tid & 31;
    const int d = (blockIdx.x * 256 + tid) >> 5;
    if (d >= V) return;

    const int base = g_starts[d];
    const int n    = g_starts[d + 1] - base;

    const uint2* __restrict__ sph = reinterpret_cast<const uint2*>(g_src_h);
    const uint2* __restrict__ dph = reinterpret_cast<const uint2*>(g_dest_h);

    const float4 dv = h4_to_f4(dph[(size_t)d * 32 + lane]);
    float4 acc = make_float4(0.f, 0.f, 0.f, 0.f);

    for (int j0 = 0; j0 < n; j0 += 32) {
        const int m = min(32, n - j0);
        int2 sc = make_int2(0, 0);
        if (lane < m) sc = g_srccls[base + j0 + lane];

        uint2 a0, a1;
        {
            int s = __shfl_sync(0xffffffffu, sc.x, 0);
            a0 = sph[(size_t)s * 32 + lane];
        }
        a1 = a0;
        if (m > 1) {
            int s = __shfl_sync(0xffffffffu, sc.x, 1);
            a1 = sph[(size_t)s * 32 + lane];
        }

        for (int j = 0; j < m; j++) {
            uint2 an = a1;
            if (j + 2 < m) {
                int s = __shfl_sync(0xffffffffu, sc.x, j + 2);
                an = sph[(size_t)s * 32 + lane];
            }
            const int c = __shfl_sync(0xffffffffu, sc.y, j);
            const float4 e = emb_sm[c * 32 + lane];
            const float4 af = h4_to_f4(a0);
            acc.x += fmaxf(af.x + dv.x + e.x, 0.f);
            acc.y += fmaxf(af.y + dv.y + e.y, 0.f);
            acc.z += fmaxf(af.z + dv.z + e.z, 0.f);
            acc.w += fmaxf(af.w + dv.w + e.w, 0.f);
            a0 = a1;
            a1 = an;
        }
    }

    reinterpret_cast<float4*>(out)[(size_t)d * 32 + lane] = acc;
}

// ---------------------------------------------------------------------------
// Launch: pre(0), hist(1), scan_a(2), proj(3), scan_b(4), build(5), accum(6).
// proj at ncu capture index 3.
// ---------------------------------------------------------------------------
extern "C" void kernel_launch(void* const* d_in, const int* in_sizes, int n_in,
                              void* d_out, int out_size) {
    const float* nv   = (const float*)d_in[0];
    const int*   esrc = (const int*)  d_in[1];
    const int*   edst = (const int*)  d_in[2];
    const int*   ecls = (const int*)  d_in[3];
    const float* Wsrc = (const float*)d_in[4];
    const float* bsrc = (const float*)d_in[5];
    const float* Wdst = (const float*)d_in[6];
    const float* bdst = (const float*)d_in[7];
    const float* emb  = (const float*)d_in[8];
    float* out = (float*)d_out;

    const int V = in_sizes[0] / DIMV;
    const int E = in_sizes[1];

    cudaFuncSetAttribute(proj_kernel, cudaFuncAttributeMaxDynamicSharedMemorySize,
                         PROJ_SMEM);

    pre_kernel<<<(MAXV * 32 + 255) / 256, 256>>>(nv, V, Wsrc, Wdst);    // 0
    hist_kernel<<<(E + 255) / 256, 256>>>(edst, E);                     // 1
    scan_a_kernel<<<SCAN_NB, 1024>>>();                                 // 2
    proj_kernel<<<PROJ_GRID, 256, PROJ_SMEM>>>(V, bsrc, bdst);          // 3
    scan_b_kernel<<<SCAN_NB, 1024>>>();                                 // 4
    build_kernel<<<(E + 255) / 256, 256>>>(esrc, edst, ecls, E);        // 5
    accum_kernel<<<(V * 32 + 255) / 256, 256>>>(emb, out, V);           // 6
}

// round 11
// speedup vs baseline: 1.8837x; 1.0560x over previous
#include <cuda_runtime.h>
#include <cuda_bf16.h>
#include <cuda_fp16.h>
#include <cstring>

// Problem constants
#define DIMV 128
#define NTYPES 32
#define MAXV 50048
#define MAXVP 53248          // 52 * 1024
#define MAXE 650000
#define SCAN_NB 52

// Scratch
__device__ char  g_w_img[2 * 73728];
__device__ __half g_src_h[(size_t)MAXV * DIMV];
__device__ __half g_dest_h[(size_t)MAXV * DIMV];
__device__ int   g_cnt[MAXVP];      // INVARIANT: all zero at kernel_launch entry
__device__ int   g_starts[MAXVP];
__device__ int   g_cursor[MAXVP];
__device__ int   g_bsum[64];
__device__ int2  g_srccls[MAXE];

// ---------------------------------------------------------------------------
// Split helpers
// ---------------------------------------------------------------------------
__device__ __forceinline__ void split_bf(float x, __nv_bfloat16& h, __nv_bfloat16& l) {
    h = __float2bfloat16_rn(x);
    l = __float2bfloat16_rn(x - __bfloat162float(h));
}

__device__ __forceinline__ unsigned pack_bf2(__nv_bfloat16 a, __nv_bfloat16 b) {
    __nv_bfloat162 t = __halves2bfloat162(a, b);
    unsigned u;
    memcpy(&u, &t, 4);
    return u;
}

// ---------------------------------------------------------------------------
// Fused pre-pass: split W into the padded smem image + edge-dest histogram.
// g_cnt is zero on entry (zeroed by scan_a of the previous run / static init).
// ---------------------------------------------------------------------------
__global__ void pre_kernel(const float* __restrict__ Wsrc,
                           const float* __restrict__ Wdst,
                           const int* __restrict__ edst, int E) {
    int idx = blockIdx.x * blockDim.x + threadIdx.x;

    if (idx < 2 * 128 * 128) {
        int m = idx >> 14;
        int e = idx & 16383;
        int k = e >> 7, n = e & 127;
        float v = (m ? Wdst : Wsrc)[e];
        __nv_bfloat16 h, l;
        split_bf(v, h, l);
        size_t base = (size_t)m * 73728 + (n >> 6) * 18432 + k * 144 + (n & 63) * 2;
        *reinterpret_cast<__nv_bfloat16*>(g_w_img + base) = h;
        *reinterpret_cast<__nv_bfloat16*>(g_w_img + base + 36864) = l;
    }

    if (idx < E) atomicAdd(&g_cnt[edst[idx]], 1);
}

// ---------------------------------------------------------------------------
// Scan phase A: 52 blocks x 1024; block-local exclusive scan of g_cnt,
// block total -> g_bsum. Re-zeroes g_cnt (maintains the invariant).
// ---------------------------------------------------------------------------
__global__ __launch_bounds__(1024) void scan_a_kernel() {
    __shared__ int wsum[32];
    const int t = threadIdx.x, lane = t & 31, wid = t >> 5;
    const int idx = blockIdx.x * 1024 + t;
    int v = g_cnt[idx];
    g_cnt[idx] = 0;                       // restore invariant for next run
    int incl = v;
#pragma unroll
    for (int o = 1; o < 32; o <<= 1) {
        int n = __shfl_up_sync(0xffffffffu, incl, o);
        if (lane >= o) incl += n;
    }
    if (lane == 31) wsum[wid] = incl;
    __syncthreads();
    if (wid == 0) {
        int ws = wsum[lane];
#pragma unroll
        for (int o = 1; o < 32; o <<= 1) {
            int n = __shfl_up_sync(0xffffffffu, ws, o);
            if (lane >= o) ws += n;
        }
        wsum[lane] = ws;
    }
    __syncthreads();
    int excl = incl - v + (wid ? wsum[wid - 1] : 0);
    g_starts[idx] = excl;
    if (t == 1023) g_bsum[blockIdx.x] = excl + v;
}

// ---------------------------------------------------------------------------
// Scan phase B: warp 0 scans the 52 block totals; all threads add offset.
// ---------------------------------------------------------------------------
__global__ __launch_bounds__(1024) void scan_b_kernel() {
    __shared__ int excl[64];
    const int t = threadIdx.x, lane = t & 31;
    if (t < 32) {
        int v0 = g_bsum[lane];
        int v1 = (32 + lane < SCAN_NB) ? g_bsum[32 + lane] : 0;
        int i0 = v0;
#pragma unroll
        for (int o = 1; o < 32; o <<= 1) {
            int n = __shfl_up_sync(0xffffffffu, i0, o);
            if (lane >= o) i0 += n;
        }
        int tot0 = __shfl_sync(0xffffffffu, i0, 31);
        int i1 = v1;
#pragma unroll
        for (int o = 1; o < 32; o <<= 1) {
            int n = __shfl_up_sync(0xffffffffu, i1, o);
            if (lane >= o) i1 += n;
        }
        excl[lane] = i0 - v0;
        excl[32 + lane] = tot0 + i1 - v1;
    }
    __syncthreads();
    const int off = excl[blockIdx.x];
    const int idx = blockIdx.x * 1024 + t;
    int s = g_starts[idx] + off;
    g_starts[idx] = s;
    g_cursor[idx] = s;
}

// ---------------------------------------------------------------------------
__global__ void build_kernel(const int* __restrict__ esrc,
                             const int* __restrict__ edst,
                             const int* __restrict__ ecls, int E) {
    int i = blockIdx.x * blockDim.x + threadIdx.x;
    if (i < E) {
        int d = edst[i];
        int pos = atomicAdd(&g_cursor[d], 1);
        g_srccls[pos] = make_int2(esrc[i], ecls[i]);
    }
}

// ---------------------------------------------------------------------------
// Persistent tensor-core projection (bf16 hi/lo x3).
// Grid = 296 CTAs (2/SM). wSel = bid & 1. W image staged ONCE per CTA;
// A is loaded as fp32 from nv and split in-kernel during staging.
// Smem: A hi/lo 36864 + W hi/lo 73728 = 110592 -> 2 CTAs/SM.
// ---------------------------------------------------------------------------
#define TROWS 64
#define A_HI  0
#define A_LO  18432
#define W_OFF 36864
#define PROJ_SMEM 110592
#define PROJ_GRID 296

#define LDSM4(r0, r1, r2, r3, addr) \
    asm volatile("ldmatrix.sync.aligned.m8n8.x4.shared.b16 {%0,%1,%2,%3}, [%4];" \
        : "=r"(r0), "=r"(r1), "=r"(r2), "=r"(r3) : "r"(addr))

#define LDSM4T(r0, r1, r2, r3, addr) \
    asm volatile("ldmatrix.sync.aligned.m8n8.x4.trans.shared.b16 {%0,%1,%2,%3}, [%4];" \
        : "=r"(r0), "=r"(r1), "=r"(r2), "=r"(r3) : "r"(addr))

#define MMA16816(d, a, b0, b1) \
    asm volatile("mma.sync.aligned.m16n8k16.row.col.f32.bf16.bf16.f32 " \
        "{%0,%1,%2,%3}, {%4,%5,%6,%7}, {%8,%9}, {%0,%1,%2,%3};" \
        : "+f"(d[0]), "+f"(d[1]), "+f"(d[2]), "+f"(d[3]) \
        : "r"(a[0]), "r"(a[1]), "r"(a[2]), "r"(a[3]), "r"(b0), "r"(b1))

__global__ __launch_bounds__(256, 2) void proj_kernel(
    const float* __restrict__ nv, int V,
    const float* __restrict__ bsrc, const float* __restrict__ bdst)
{
    extern __shared__ __align__(16) char smem[];
    unsigned smemu;
    asm("{ .reg .u64 t; cvta.to.shared.u64 t, %1; cvt.u32.u64 %0, t; }"
        : "=r"(smemu) : "l"(smem));

    const int tid = threadIdx.x;
    const int wSel = blockIdx.x & 1;
    const int tile0 = blockIdx.x >> 1;
    const int nTiles = (V + TROWS - 1) / TROWS;

    // stage W ONCE
    {
        const uint4* wsrc = reinterpret_cast<const uint4*>(g_w_img + wSel * 73728);
        uint4* wdst = reinterpret_cast<uint4*>(smem + W_OFF);
        for (int idx = tid; idx < 4608; idx += 256) wdst[idx] = wsrc[idx];
    }

    const float* __restrict__ bias = wSel ? bdst : bsrc;
    __half* __restrict__ outh = wSel ? g_dest_h : g_src_h;

    const int lane = tid & 31, wid = tid >> 5;
    const int warp_m = wid >> 2;
    const int warp_n = wid & 3;
    const int sel = lane >> 3, li = lane & 7;

    const unsigned wB = smemu + W_OFF + (warp_n >> 1) * 18432;
    const int ncol0 = (warp_n & 1) * 32;

    float bv[4][2];
#pragma unroll
    for (int j = 0; j < 4; j++) {
        int col = warp_n * 32 + j * 8 + (lane & 3) * 2;
        bv[j][0] = bias[col];
        bv[j][1] = bias[col + 1];
    }

    const float4* nv4 = reinterpret_cast<const float4*>(nv);

    for (int tile = tile0; tile < nTiles; tile += 148) {
        const int row0 = tile * TROWS;

        __syncthreads();   // previous iteration's smem reads done (covers W on iter 0)

        // ---- stage A: load fp32, split to bf16 hi/lo, store padded ----
        // 64 rows x 32 float4 = 2048 chunks; idx -> r = idx>>5, q = idx&31
        // k = q*4: half h = q>>4, in-half kl = (q&15)*4
#pragma unroll 2
        for (int idx = tid; idx < 2048; idx += 256) {
            int r = idx >> 5, q = idx & 31;
            int gr = row0 + r;
            float4 v = make_float4(0.f, 0.f, 0.f, 0.f);
            if (gr < V) v = nv4[(size_t)gr * 32 + q];
            __nv_bfloat16 h0, h1, h2, h3, l0, l1, l2, l3;
            split_bf(v.x, h0, l0); split_bf(v.y, h1, l1);
            split_bf(v.z, h2, l2); split_bf(v.w, h3, l3);
            size_t dst = (size_t)(q >> 4) * 9216 + r * 144 + (q & 15) * 8;
            *reinterpret_cast<uint2*>(smem + A_HI + dst) =
                make_uint2(pack_bf2(h0, h1), pack_bf2(h2, h3));
            *reinterpret_cast<uint2*>(smem + A_LO + dst) =
                make_uint2(pack_bf2(l0, l1), pack_bf2(l2, l3));
        }
        __syncthreads();

        float acc[2][4][4];
#pragma unroll
        for (int j = 0; j < 4; j++)
#pragma unroll
            for (int m = 0; m < 2; m++) {
                acc[m][j][0] = bv[j][0]; acc[m][j][1] = bv[j][1];
                acc[m][j][2] = bv[j][0]; acc[m][j][3] = bv[j][1];
            }

#pragma unroll
        for (int h = 0; h < 2; h++) {
#pragma unroll
            for (int kf = 0; kf < 4; kf++) {
                unsigned ah[2][4], al[2][4];
                {
                    int arow = warp_m * 32 + li + (sel & 1) * 8;
                    int kch = kf * 16 + (sel >> 1) * 8;
                    unsigned a0 = smemu + A_HI + h * 9216 + arow * 144 + kch * 2;
                    LDSM4(ah[0][0], ah[0][1], ah[0][2], ah[0][3], a0);
                    LDSM4(ah[1][0], ah[1][1], ah[1][2], ah[1][3], a0 + 16 * 144);
                    unsigned a1 = a0 + (A_LO - A_HI);
                    LDSM4(al[0][0], al[0][1], al[0][2], al[0][3], a1);
                    LDSM4(al[1][0], al[1][1], al[1][2], al[1][3], a1 + 16 * 144);
                }
                const int krow = h * 64 + kf * 16 + li + (sel & 1) * 8;
#pragma unroll
                for (int jj = 0; jj < 2; jj++) {
                    unsigned bh[4], bl[4];
                    int nch = ncol0 + jj * 16 + (sel >> 1) * 8;
                    unsigned boff = wB + krow * 144 + nch * 2;
                    LDSM4T(bh[0], bh[1], bh[2], bh[3], boff);
                    LDSM4T(bl[0], bl[1], bl[2], bl[3], boff + 36864);
#pragma unroll
                    for (int m = 0; m < 2; m++) {
                        MMA16816(acc[m][2 * jj + 0], ah[m], bh[0], bh[1]);
                        MMA16816(acc[m][2 * jj + 1], ah[m], bh[2], bh[3]);
                        MMA16816(acc[m][2 * jj + 0], ah[m], bl[0], bl[1]);
                        MMA16816(acc[m][2 * jj + 1], ah[m], bl[2], bl[3]);
                        MMA16816(acc[m][2 * jj + 0], al[m], bh[0], bh[1]);
                        MMA16816(acc[m][2 * jj + 1], al[m], bh[2], bh[3]);
                    }
                }
            }
        }

#pragma unroll
        for (int m = 0; m < 2; m++) {
            int rlo = row0 + warp_m * 32 + m * 16 + (lane >> 2);
#pragma unroll
            for (int j = 0; j < 4; j++) {
                int col = warp_n * 32 + j * 8 + (lane & 3) * 2;
                *reinterpret_cast<__half2*>(&outh[(size_t)rlo * 128 + col]) =
                    __floats2half2_rn(acc[m][j][0], acc[m][j][1]);
                *reinterpret_cast<__half2*>(&outh[(size_t)(rlo + 8) * 128 + col]) =
                    __floats2half2_rn(acc[m][j][2], acc[m][j][3]);
            }
        }
    }
}

// ---------------------------------------------------------------------------
// Segment-accumulate: warp per dest node, fp16 gathers, depth-3 pipeline.
// ---------------------------------------------------------------------------
__device__ __forceinline__ float4 h4_to_f4(uint2 u) {
    __half2 h0, h1;
    memcpy(&h0, &u.x, 4);
    memcpy(&h1, &u.y, 4);
    float2 f0 = __half22float2(h0);
    float2 f1 = __half22float2(h1);
    return make_float4(f0.x, f0.y, f1.x, f1.y);
}

__global__ __launch_bounds__(256) void accum_kernel(
    const float* __restrict__ emb, float* __restrict__ out, int V)
{
    __shared__ float4 emb_sm[NTYPES * 32];
    const int tid = threadIdx.x;
    for (int i = tid; i < NTYPES * 32; i += 256)
        emb_sm[i] = reinterpret_cast<const float4*>(emb)[i];
    __syncthreads();

    const int lane = tid & 31;
    const int d = (blockIdx.x * 256 + tid) >> 5;
    if (d >= V) return;

    const int base = g_starts[d];
    const int n    = g_starts[d + 1] - base;

    const uint2* __restrict__ sph = reinterpret_cast<const uint2*>(g_src_h);
    const uint2* __restrict__ dph = reinterpret_cast<const uint2*>(g_dest_h);

    const float4 dv = h4_to_f4(dph[(size_t)d * 32 + lane]);
    float4 acc = make_float4(0.f, 0.f, 0.f, 0.f);

    for (int j0 = 0; j0 < n; j0 += 32) {
        const int m = min(32, n - j0);
        int2 sc = make_int2(0, 0);
        if (lane < m) sc = g_srccls[base + j0 + lane];

        uint2 a0, a1;
        {
            int s = __shfl_sync(0xffffffffu, sc.x, 0);
            a0 = sph[(size_t)s * 32 + lane];
        }
        a1 = a0;
        if (m > 1) {
            int s = __shfl_sync(0xffffffffu, sc.x, 1);
            a1 = sph[(size_t)s * 32 + lane];
        }

        for (int j = 0; j < m; j++) {
            uint2 an = a1;
            if (j + 2 < m) {
                int s = __shfl_sync(0xffffffffu, sc.x, j + 2);
                an = sph[(size_t)s * 32 + lane];
            }
            const int c = __shfl_sync(0xffffffffu, sc.y, j);
            const float4 e = emb_sm[c * 32 + lane];
            const float4 af = h4_to_f4(a0);
            acc.x += fmaxf(af.x + dv.x + e.x, 0.f);
            acc.y += fmaxf(af.y + dv.y + e.y, 0.f);
            acc.z += fmaxf(af.z + dv.z + e.z, 0.f);
            acc.w += fmaxf(af.w + dv.w + e.w, 0.f);
            a0 = a1;
            a1 = an;
        }
    }

    reinterpret_cast<float4*>(out)[(size_t)d * 32 + lane] = acc;
}

// ---------------------------------------------------------------------------
// Launch: pre(0), scan_a(1), scan_b(2), proj(3), build(4), accum(5).
// proj at ncu capture index 3.
// ---------------------------------------------------------------------------
extern "C" void kernel_launch(void* const* d_in, const int* in_sizes, int n_in,
                              void* d_out, int out_size) {
    const float* nv   = (const float*)d_in[0];
    const int*   esrc = (const int*)  d_in[1];
    const int*   edst = (const int*)  d_in[2];
    const int*   ecls = (const int*)  d_in[3];
    const float* Wsrc = (const float*)d_in[4];
    const float* bsrc = (const float*)d_in[5];
    const float* Wdst = (const float*)d_in[6];
    const float* bdst = (const float*)d_in[7];
    const float* emb  = (const float*)d_in[8];
    float* out = (float*)d_out;

    const int V = in_sizes[0] / DIMV;
    const int E = in_sizes[1];

    cudaFuncSetAttribute(proj_kernel, cudaFuncAttributeMaxDynamicSharedMemorySize,
                         PROJ_SMEM);

    pre_kernel<<<(E + 255) / 256, 256>>>(Wsrc, Wdst, edst, E);          // 0
    scan_a_kernel<<<SCAN_NB, 1024>>>();                                 // 1
    scan_b_kernel<<<SCAN_NB, 1024>>>();                                 // 2
    proj_kernel<<<PROJ_GRID, 256, PROJ_SMEM>>>(nv, V, bsrc, bdst);      // 3
    build_kernel<<<(E + 255) / 256, 256>>>(esrc, edst, ecls, E);        // 4
    accum_kernel<<<(V * 32 + 255) / 256, 256>>>(emb, out, V);           // 5
}

// round 17
// speedup vs baseline: 1.9155x; 1.0169x over previous
#include <cuda_runtime.h>
#include <cuda_bf16.h>
#include <cuda_fp16.h>
#include <cstring>
#include <cstdint>

// Problem constants
#define DIMV 128
#define NTYPES 32
#define MAXV 50048
#define MAXVP 53248          // 52 * 1024
#define MAXE 650000
#define SCAN_NB 52

// Scratch
__device__ char  g_w_img[2 * 73728];   // smem-image of both W (hi+lo, padded 144B rows)
__device__ __half g_src_h[(size_t)MAXV * DIMV];
__device__ __half g_dest_h[(size_t)MAXV * DIMV];
__device__ int   g_cnt[MAXVP];         // INVARIANT: all zero at kernel_launch entry
__device__ int   g_starts[MAXVP];      // block-LOCAL exclusive starts (scan_a)
__device__ int   g_cursor[MAXVP];      // block-LOCAL cursors
__device__ int   g_bsum[64];           // per-scan-block totals
__device__ int2  g_srccls[MAXE];

// ---------------------------------------------------------------------------
// Split helpers
// ---------------------------------------------------------------------------
__device__ __forceinline__ void split_bf(float x, __nv_bfloat16& h, __nv_bfloat16& l) {
    h = __float2bfloat16_rn(x);
    l = __float2bfloat16_rn(x - __bfloat162float(h));
}

__device__ __forceinline__ unsigned pack_bf2(__nv_bfloat16 a, __nv_bfloat16 b) {
    __nv_bfloat162 t = __halves2bfloat162(a, b);
    unsigned u;
    memcpy(&u, &t, 4);
    return u;
}

// Inline 52-entry exclusive scan of g_bsum into smem (one warp helper).
// Call with a full block; result in excl52[0..51] after __syncthreads().
__device__ __forceinline__ void offsets52(int* excl52, int tid) {
    if (tid < 32) {
        int lane = tid;
        int v0 = g_bsum[lane];
        int v1 = (32 + lane < SCAN_NB) ? g_bsum[32 + lane] : 0;
        int i0 = v0;
#pragma unroll
        for (int o = 1; o < 32; o <<= 1) {
            int n = __shfl_up_sync(0xffffffffu, i0, o);
            if (lane >= o) i0 += n;
        }
        int tot0 = __shfl_sync(0xffffffffu, i0, 31);
        int i1 = v1;
#pragma unroll
        for (int o = 1; o < 32; o <<= 1) {
            int n = __shfl_up_sync(0xffffffffu, i1, o);
            if (lane >= o) i1 += n;
        }
        excl52[lane] = i0 - v0;
        if (32 + lane < 64) excl52[32 + lane] = tot0 + i1 - v1;
    }
    __syncthreads();
}

// ---------------------------------------------------------------------------
// Branch A kernels: histogram -> scan_a -> build
// ---------------------------------------------------------------------------
__global__ void hist_kernel(const int* __restrict__ edst, int E) {
    int i = blockIdx.x * blockDim.x + threadIdx.x;
    if (i < E) atomicAdd(&g_cnt[edst[i]], 1);
}

__global__ __launch_bounds__(1024) void scan_a_kernel() {
    __shared__ int wsum[32];
    const int t = threadIdx.x, lane = t & 31, wid = t >> 5;
    const int idx = blockIdx.x * 1024 + t;
    int v = g_cnt[idx];
    g_cnt[idx] = 0;                       // restore invariant for next run
    int incl = v;
#pragma unroll
    for (int o = 1; o < 32; o <<= 1) {
        int n = __shfl_up_sync(0xffffffffu, incl, o);
        if (lane >= o) incl += n;
    }
    if (lane == 31) wsum[wid] = incl;
    __syncthreads();
    if (wid == 0) {
        int ws = wsum[lane];
#pragma unroll
        for (int o = 1; o < 32; o <<= 1) {
            int n = __shfl_up_sync(0xffffffffu, ws, o);
            if (lane >= o) ws += n;
        }
        wsum[lane] = ws;
    }
    __syncthreads();
    int excl = incl - v + (wid ? wsum[wid - 1] : 0);
    g_starts[idx] = excl;                 // LOCAL exclusive start
    g_cursor[idx] = excl;                 // LOCAL cursor
    if (t == 1023) g_bsum[blockIdx.x] = excl + v;
}

__global__ __launch_bounds__(256) void build_kernel(
    const int* __restrict__ esrc, const int* __restrict__ edst,
    const int* __restrict__ ecls, int E)
{
    __shared__ int excl52[64];
    offsets52(excl52, threadIdx.x);

    int i = blockIdx.x * blockDim.x + threadIdx.x;
    if (i < E) {
        int d = edst[i];
        int pos = atomicAdd(&g_cursor[d], 1) + excl52[d >> 10];
        g_srccls[pos] = make_int2(esrc[i], ecls[i]);
    }
}

// ---------------------------------------------------------------------------
// Branch B: W split (padded 144B-row image) then persistent proj.
// ---------------------------------------------------------------------------
__global__ void w_split_kernel(const float* __restrict__ Wsrc,
                               const float* __restrict__ Wdst) {
    int idx = blockIdx.x * blockDim.x + threadIdx.x;   // 2*128*128
    if (idx >= 2 * 128 * 128) return;
    int m = idx >> 14;
    int e = idx & 16383;
    int k = e >> 7, n = e & 127;
    float v = (m ? Wdst : Wsrc)[e];
    __nv_bfloat16 h, l;
    split_bf(v, h, l);
    size_t base = (size_t)m * 73728 + (n >> 6) * 18432 + k * 144 + (n & 63) * 2;
    *reinterpret_cast<__nv_bfloat16*>(g_w_img + base) = h;
    *reinterpret_cast<__nv_bfloat16*>(g_w_img + base + 36864) = l;
}

// Persistent mma.sync proj (R11 version, best passing).
#define TROWS 64
#define A_HI  0
#define A_LO  18432
#define W_OFF 36864
#define PROJ_SMEM 110592
#define PROJ_GRID 296

#define LDSM4(r0, r1, r2, r3, addr) \
    asm volatile("ldmatrix.sync.aligned.m8n8.x4.shared.b16 {%0,%1,%2,%3}, [%4];" \
        : "=r"(r0), "=r"(r1), "=r"(r2), "=r"(r3) : "r"(addr))

#define LDSM4T(r0, r1, r2, r3, addr) \
    asm volatile("ldmatrix.sync.aligned.m8n8.x4.trans.shared.b16 {%0,%1,%2,%3}, [%4];" \
        : "=r"(r0), "=r"(r1), "=r"(r2), "=r"(r3) : "r"(addr))

#define MMA16816(d, a, b0, b1) \
    asm volatile("mma.sync.aligned.m16n8k16.row.col.f32.bf16.bf16.f32 " \
        "{%0,%1,%2,%3}, {%4,%5,%6,%7}, {%8,%9}, {%0,%1,%2,%3};" \
        : "+f"(d[0]), "+f"(d[1]), "+f"(d[2]), "+f"(d[3]) \
        : "r"(a[0]), "r"(a[1]), "r"(a[2]), "r"(a[3]), "r"(b0), "r"(b1))

__global__ __launch_bounds__(256, 2) void proj_kernel(
    const float* __restrict__ nv, int V,
    const float* __restrict__ bsrc, const float* __restrict__ bdst)
{
    extern __shared__ __align__(16) char smem[];
    unsigned smemu;
    asm("{ .reg .u64 t; cvta.to.shared.u64 t, %1; cvt.u32.u64 %0, t; }"
        : "=r"(smemu) : "l"(smem));

    const int tid = threadIdx.x;
    const int wSel = blockIdx.x & 1;
    const int tile0 = blockIdx.x >> 1;
    const int nTiles = (V + TROWS - 1) / TROWS;

    // stage W ONCE
    {
        const uint4* wsrc = reinterpret_cast<const uint4*>(g_w_img + wSel * 73728);
        uint4* wdst = reinterpret_cast<uint4*>(smem + W_OFF);
        for (int idx = tid; idx < 4608; idx += 256) wdst[idx] = wsrc[idx];
    }

    const float* __restrict__ bias = wSel ? bdst : bsrc;
    __half* __restrict__ outh = wSel ? g_dest_h : g_src_h;

    const int lane = tid & 31, wid = tid >> 5;
    const int warp_m = wid >> 2;
    const int warp_n = wid & 3;
    const int sel = lane >> 3, li = lane & 7;

    const unsigned wB = smemu + W_OFF + (warp_n >> 1) * 18432;
    const int ncol0 = (warp_n & 1) * 32;

    float bv[4][2];
#pragma unroll
    for (int j = 0; j < 4; j++) {
        int col = warp_n * 32 + j * 8 + (lane & 3) * 2;
        bv[j][0] = bias[col];
        bv[j][1] = bias[col + 1];
    }

    const float4* nv4 = reinterpret_cast<const float4*>(nv);

    for (int tile = tile0; tile < nTiles; tile += 148) {
        const int row0 = tile * TROWS;

        __syncthreads();   // prior iteration's smem reads done (covers W on iter 0)

        // stage A: load fp32, split to bf16 hi/lo, store padded
#pragma unroll 2
        for (int idx = tid; idx < 2048; idx += 256) {
            int r = idx >> 5, q = idx & 31;
            int gr = row0 + r;
            float4 v = make_float4(0.f, 0.f, 0.f, 0.f);
            if (gr < V) v = nv4[(size_t)gr * 32 + q];
            __nv_bfloat16 h0, h1, h2, h3, l0, l1, l2, l3;
            split_bf(v.x, h0, l0); split_bf(v.y, h1, l1);
            split_bf(v.z, h2, l2); split_bf(v.w, h3, l3);
            size_t dst = (size_t)(q >> 4) * 9216 + r * 144 + (q & 15) * 8;
            *reinterpret_cast<uint2*>(smem + A_HI + dst) =
                make_uint2(pack_bf2(h0, h1), pack_bf2(h2, h3));
            *reinterpret_cast<uint2*>(smem + A_LO + dst) =
                make_uint2(pack_bf2(l0, l1), pack_bf2(l2, l3));
        }
        __syncthreads();

        float acc[2][4][4];
#pragma unroll
        for (int j = 0; j < 4; j++)
#pragma unroll
            for (int m = 0; m < 2; m++) {
                acc[m][j][0] = bv[j][0]; acc[m][j][1] = bv[j][1];
                acc[m][j][2] = bv[j][0]; acc[m][j][3] = bv[j][1];
            }

#pragma unroll
        for (int h = 0; h < 2; h++) {
#pragma unroll
            for (int kf = 0; kf < 4; kf++) {
                unsigned ah[2][4], al[2][4];
                {
                    int arow = warp_m * 32 + li + (sel & 1) * 8;
                    int kch = kf * 16 + (sel >> 1) * 8;
                    unsigned a0 = smemu + A_HI + h * 9216 + arow * 144 + kch * 2;
                    LDSM4(ah[0][0], ah[0][1], ah[0][2], ah[0][3], a0);
                    LDSM4(ah[1][0], ah[1][1], ah[1][2], ah[1][3], a0 + 16 * 144);
                    unsigned a1 = a0 + (A_LO - A_HI);
                    LDSM4(al[0][0], al[0][1], al[0][2], al[0][3], a1);
                    LDSM4(al[1][0], al[1][1], al[1][2], al[1][3], a1 + 16 * 144);
                }
                const int krow = h * 64 + kf * 16 + li + (sel & 1) * 8;
#pragma unroll
                for (int jj = 0; jj < 2; jj++) {
                    unsigned bh[4], bl[4];
                    int nch = ncol0 + jj * 16 + (sel >> 1) * 8;
                    unsigned boff = wB + krow * 144 + nch * 2;
                    LDSM4T(bh[0], bh[1], bh[2], bh[3], boff);
                    LDSM4T(bl[0], bl[1], bl[2], bl[3], boff + 36864);
#pragma unroll
                    for (int m = 0; m < 2; m++) {
                        MMA16816(acc[m][2 * jj + 0], ah[m], bh[0], bh[1]);
                        MMA16816(acc[m][2 * jj + 1], ah[m], bh[2], bh[3]);
                        MMA16816(acc[m][2 * jj + 0], ah[m], bl[0], bl[1]);
                        MMA16816(acc[m][2 * jj + 1], ah[m], bl[2], bl[3]);
                        MMA16816(acc[m][2 * jj + 0], al[m], bh[0], bh[1]);
                        MMA16816(acc[m][2 * jj + 1], al[m], bh[2], bh[3]);
                    }
                }
            }
        }

#pragma unroll
        for (int m = 0; m < 2; m++) {
            int rlo = row0 + warp_m * 32 + m * 16 + (lane >> 2);
#pragma unroll
            for (int j = 0; j < 4; j++) {
                int col = warp_n * 32 + j * 8 + (lane & 3) * 2;
                *reinterpret_cast<__half2*>(&outh[(size_t)rlo * 128 + col]) =
                    __floats2half2_rn(acc[m][j][0], acc[m][j][1]);
                *reinterpret_cast<__half2*>(&outh[(size_t)(rlo + 8) * 128 + col]) =
                    __floats2half2_rn(acc[m][j][2], acc[m][j][3]);
            }
        }
    }
}

// ---------------------------------------------------------------------------
// Segment-accumulate: warp per dest node, fp16 gathers, depth-3 pipeline.
// Inline 52-offset scan for absolute segment addresses.
// ---------------------------------------------------------------------------
__device__ __forceinline__ float4 h4_to_f4(uint2 u) {
    __half2 h0, h1;
    memcpy(&h0, &u.x, 4);
    memcpy(&h1, &u.y, 4);
    float2 f0 = __half22float2(h0);
    float2 f1 = __half22float2(h1);
    return make_float4(f0.x, f0.y, f1.x, f1.y);
}

__global__ __launch_bounds__(256) void accum_kernel(
    const float* __restrict__ emb, float* __restrict__ out, int V)
{
    __shared__ float4 emb_sm[NTYPES * 32];
    __shared__ int excl52[64];
    const int tid = threadIdx.x;
    for (int i = tid; i < NTYPES * 32; i += 256)
        emb_sm[i] = reinterpret_cast<const float4*>(emb)[i];
    offsets52(excl52, tid);               // includes __syncthreads()

    const int lane = tid & 31;
    const int d = (blockIdx.x * 256 + tid) >> 5;
    if (d >= V) return;

    const int base = g_starts[d] + excl52[d >> 10];
    const int end  = g_starts[d + 1] + excl52[(d + 1) >> 10];
    const int n    = end - base;

    const uint2* __restrict__ sph = reinterpret_cast<const uint2*>(g_src_h);
    const uint2* __restrict__ dph = reinterpret_cast<const uint2*>(g_dest_h);

    const float4 dv = h4_to_f4(dph[(size_t)d * 32 + lane]);
    float4 acc = make_float4(0.f, 0.f, 0.f, 0.f);

    for (int j0 = 0; j0 < n; j0 += 32) {
        const int m = min(32, n - j0);
        int2 sc = make_int2(0, 0);
        if (lane < m) sc = g_srccls[base + j0 + lane];

        uint2 a0, a1;
        {
            int s = __shfl_sync(0xffffffffu, sc.x, 0);
            a0 = sph[(size_t)s * 32 + lane];
        }
        a1 = a0;
        if (m > 1) {
            int s = __shfl_sync(0xffffffffu, sc.x, 1);
            a1 = sph[(size_t)s * 32 + lane];
        }

        for (int j = 0; j < m; j++) {
            uint2 an = a1;
            if (j + 2 < m) {
                int s = __shfl_sync(0xffffffffu, sc.x, j + 2);
                an = sph[(size_t)s * 32 + lane];
            }
            const int c = __shfl_sync(0xffffffffu, sc.y, j);
            const float4 e = emb_sm[c * 32 + lane];
            const float4 af = h4_to_f4(a0);
            acc.x += fmaxf(af.x + dv.x + e.x, 0.f);
            acc.y += fmaxf(af.y + dv.y + e.y, 0.f);
            acc.z += fmaxf(af.z + dv.z + e.z, 0.f);
            acc.w += fmaxf(af.w + dv.w + e.w, 0.f);
            a0 = a1;
            a1 = an;
        }
    }

    reinterpret_cast<float4*>(out)[(size_t)d * 32 + lane] = acc;
}

// ---------------------------------------------------------------------------
// Launch with a forked second stream (graph-capture-legal fork/join):
//   stream0: hist -> scan_a -> build ----\
//   s2:      w_split -> proj ------------+--> accum (stream0)
// Kernel issue order: hist(0), scan_a(1), w_split(2), proj(3), build(4),
// accum(5) — proj stays at ncu capture index 3.
// ---------------------------------------------------------------------------
extern "C" void kernel_launch(void* const* d_in, const int* in_sizes, int n_in,
                              void* d_out, int out_size) {
    const float* nv   = (const float*)d_in[0];
    const int*   esrc = (const int*)  d_in[1];
    const int*   edst = (const int*)  d_in[2];
    const int*   ecls = (const int*)  d_in[3];
    const float* Wsrc = (const float*)d_in[4];
    const float* bsrc = (const float*)d_in[5];
    const float* Wdst = (const float*)d_in[6];
    const float* bdst = (const float*)d_in[7];
    const float* emb  = (const float*)d_in[8];
    float* out = (float*)d_out;

    const int V = in_sizes[0] / DIMV;
    const int E = in_sizes[1];

    cudaFuncSetAttribute(proj_kernel, cudaFuncAttributeMaxDynamicSharedMemorySize,
                         PROJ_SMEM);

    cudaStream_t s2;
    cudaStreamCreateWithFlags(&s2, cudaStreamNonBlocking);
    cudaEvent_t eFork, eJoin;
    cudaEventCreateWithFlags(&eFork, cudaEventDisableTiming);
    cudaEventCreateWithFlags(&eJoin, cudaEventDisableTiming);

    // fork
    cudaEventRecord(eFork, 0);

    // branch A (stream 0): sort chain
    hist_kernel<<<(E + 255) / 256, 256>>>(edst, E);                       // 0
    scan_a_kernel<<<SCAN_NB, 1024>>>();                                   // 1

    // branch B (s2): weight split + projection
    cudaStreamWaitEvent(s2, eFork, 0);
    w_split_kernel<<<(2 * 128 * 128 + 255) / 256, 256, 0, s2>>>(Wsrc, Wdst); // 2
    proj_kernel<<<PROJ_GRID, 256, PROJ_SMEM, s2>>>(nv, V, bsrc, bdst);       // 3

    // branch A continues
    build_kernel<<<(E + 255) / 256, 256>>>(esrc, edst, ecls, E);          // 4

    // join: accum needs proj (s2) + build (stream 0)
    cudaEventRecord(eJoin, s2);
    cudaStreamWaitEvent(0, eJoin, 0);
    accum_kernel<<<(V * 32 + 255) / 256, 256>>>(emb, out, V);             // 5
}